// round 2
// baseline (speedup 1.0000x reference)
#include <cuda_runtime.h>
#include <math.h>

#define TT 256
#define BB 128
#define EE 256
#define HH 512
#define G4 2048   // 4*H
#define NK 7
#define NCTAS 128 // persistent recurrent grid (must all be co-resident)

// ---------------- scratch (device globals; no mallocs allowed) ----------------
__device__ float g_G[134217728];   // [dir][t][j][b] : 2*256*2048*128  (536 MB)
__device__ float g_h[33554432];    // [dir][t][k][b] : 2*256*512*128   (134 MB)
__device__ float g_em[229376];     // [t][b][k]
__device__ float g_lossB[BB];
__device__ unsigned g_bar_cnt;     // monotonic arrival counter
__device__ unsigned g_bar_gen;     // released phase

// ---------------- device-wide barrier (all CTAs resident) ----------------
__device__ __forceinline__ void grid_sync() {
    __threadfence();
    __syncthreads();
    if (threadIdx.x == 0) {
        unsigned a = atomicAdd(&g_bar_cnt, 1u) + 1u;
        unsigned need = (a - 1u) / NCTAS + 1u;
        if (a % NCTAS == 0u) {
            atomicExch(&g_bar_gen, need);
        } else {
            while (atomicAdd(&g_bar_gen, 0u) < need) { __nanosleep(64); }
        }
        __threadfence();
    }
    __syncthreads();
}

__device__ __forceinline__ float sigmoidf_(float x) { return 1.0f / (1.0f + expf(-x)); }

// ---------------- kernel 1: fused embedding gather + input GEMM + bias ----------------
// C[dir][t][j][b] = bias[j] + sum_k embed[idx[t,b],k] * Wih[j,k]
// tile: 128 (b) x 128 (j), BK=8, 256 threads, 8x8 per thread
__global__ void __launch_bounds__(256) input_gemm(
    const int* __restrict__ inputData, const float* __restrict__ embed,
    const float* __restrict__ WihF, const float* __restrict__ WihB,
    const float* __restrict__ bihF, const float* __restrict__ bhhF,
    const float* __restrict__ bihB, const float* __restrict__ bhhB)
{
    const int dir = blockIdx.z;
    const int t   = blockIdx.y;
    const int j0  = blockIdx.x * 128;
    const float* __restrict__ Wih = dir ? WihB : WihF;
    const float* __restrict__ bih = dir ? bihB : bihF;
    const float* __restrict__ bhh = dir ? bhhB : bhhF;

    __shared__ float As[8][128];
    __shared__ float Bs[8][128];
    __shared__ int   rows[128];

    const int tid = threadIdx.x;
    if (tid < 128) rows[tid] = inputData[t * BB + tid];
    __syncthreads();

    const int tx = tid & 15;   // j octet
    const int ty = tid >> 4;   // b octet

    float acc[8][8];
#pragma unroll
    for (int i = 0; i < 8; i++)
#pragma unroll
        for (int j = 0; j < 8; j++) acc[i][j] = 0.0f;

    const int lm = tid >> 1;          // 0..127
    const int lk = (tid & 1) * 4;     // 0 or 4

    for (int k0 = 0; k0 < EE; k0 += 8) {
        float4 av = *(const float4*)(embed + (size_t)rows[lm] * EE + k0 + lk);
        float4 bv = *(const float4*)(Wih   + (size_t)(j0 + lm) * EE + k0 + lk);
        __syncthreads();
        As[lk + 0][lm] = av.x; As[lk + 1][lm] = av.y; As[lk + 2][lm] = av.z; As[lk + 3][lm] = av.w;
        Bs[lk + 0][lm] = bv.x; Bs[lk + 1][lm] = bv.y; Bs[lk + 2][lm] = bv.z; Bs[lk + 3][lm] = bv.w;
        __syncthreads();
#pragma unroll
        for (int kk = 0; kk < 8; kk++) {
            float a0[8], b0[8];
            *(float4*)(a0)     = *(const float4*)(&As[kk][ty * 8]);
            *(float4*)(a0 + 4) = *(const float4*)(&As[kk][ty * 8 + 4]);
            *(float4*)(b0)     = *(const float4*)(&Bs[kk][tx * 8]);
            *(float4*)(b0 + 4) = *(const float4*)(&Bs[kk][tx * 8 + 4]);
#pragma unroll
            for (int i = 0; i < 8; i++)
#pragma unroll
                for (int j = 0; j < 8; j++) acc[i][j] += a0[i] * b0[j];
        }
    }

    const size_t base = (size_t)(dir * TT + t) * G4;
#pragma unroll
    for (int jj = 0; jj < 8; jj++) {
        const int j = j0 + tx * 8 + jj;
        const float bias = bih[j] + bhh[j];
        float4 v0 = make_float4(acc[0][jj] + bias, acc[1][jj] + bias, acc[2][jj] + bias, acc[3][jj] + bias);
        float4 v1 = make_float4(acc[4][jj] + bias, acc[5][jj] + bias, acc[6][jj] + bias, acc[7][jj] + bias);
        float* dst = g_G + (base + j) * BB + ty * 8;
        *(float4*)(dst)     = v0;
        *(float4*)(dst + 4) = v1;
    }
}

// ---------------- kernel 2: persistent BiLSTM recurrence ----------------
// 128 CTAs: bid>>6 = dir, (bid&63)*8 = hc0 (8 hidden columns, all 4 gates).
// smem: w_s[512][32] (Whh slice, loaded once), h_s[128][128] (h K-chunk).
// 256 threads: tx=b-quad (0..31), ty=hc (0..7). c state in registers.
__global__ void __launch_bounds__(256, 1) recurrent(
    const float* __restrict__ WhhF, const float* __restrict__ WhhB)
{
    extern __shared__ float smem[];
    float* w_s = smem;           // 512*32
    float* h_s = smem + 16384;   // 128*128

    const int tid = threadIdx.x;
    const int tx = tid & 31;
    const int ty = tid >> 5;
    const int bid = blockIdx.x;
    const int dir = bid >> 6;
    const int hc0 = (bid & 63) * 8;
    const float* __restrict__ Whh = dir ? WhhB : WhhF;

    // one-time Whh slice load: w_s[k][r], r = hcl*4+g, j = g*512 + hc0 + hcl
#pragma unroll
    for (int it = 0; it < 16; it++) {
        int lin = it * 256 + tid;     // float4 units, 0..4095
        int r = lin >> 7;
        int kq = lin & 127;
        int j = (r & 3) * HH + hc0 + (r >> 2);
        float4 v = *(const float4*)(Whh + (size_t)j * HH + kq * 4);
        w_s[(kq * 4 + 0) * 32 + r] = v.x;
        w_s[(kq * 4 + 1) * 32 + r] = v.y;
        w_s[(kq * 4 + 2) * 32 + r] = v.z;
        w_s[(kq * 4 + 3) * 32 + r] = v.w;
    }
    __syncthreads();

    float c[4] = {0.f, 0.f, 0.f, 0.f};

    for (int s = 0; s < TT; s++) {
        const int t = dir ? (TT - 1 - s) : s;
        float acc[4][4];
#pragma unroll
        for (int bi = 0; bi < 4; bi++)
#pragma unroll
            for (int g = 0; g < 4; g++) acc[bi][g] = 0.0f;

        if (s > 0) {
            const int tp = dir ? (t + 1) : (t - 1);
            const float4* hsrc = (const float4*)(g_h + (size_t)(dir * TT + tp) * HH * BB);
            for (int k0 = 0; k0 < HH; k0 += 128) {
                __syncthreads();
#pragma unroll
                for (int i = 0; i < 16; i++) {
                    int lin = i * 256 + tid;
                    ((float4*)h_s)[lin] = __ldcg(hsrc + k0 * 32 + lin);
                }
                __syncthreads();
#pragma unroll 4
                for (int kk = 0; kk < 128; kk++) {
                    float4 a = *(const float4*)(h_s + kk * 128 + tx * 4);
                    float4 w = *(const float4*)(w_s + (k0 + kk) * 32 + ty * 4);
                    acc[0][0] += a.x * w.x; acc[0][1] += a.x * w.y; acc[0][2] += a.x * w.z; acc[0][3] += a.x * w.w;
                    acc[1][0] += a.y * w.x; acc[1][1] += a.y * w.y; acc[1][2] += a.y * w.z; acc[1][3] += a.y * w.w;
                    acc[2][0] += a.z * w.x; acc[2][1] += a.z * w.y; acc[2][2] += a.z * w.z; acc[2][3] += a.z * w.w;
                    acc[3][0] += a.w * w.x; acc[3][1] += a.w * w.y; acc[3][2] += a.w * w.z; acc[3][3] += a.w * w.w;
                }
            }
        }

        // gate preactivations (input part + bias) and elementwise LSTM cell
        const float4* Gp = (const float4*)(g_G + (size_t)(dir * TT + t) * G4 * BB);
        float4 gI = __ldcg(Gp + (size_t)(0 * HH + hc0 + ty) * 32 + tx);
        float4 gF = __ldcg(Gp + (size_t)(1 * HH + hc0 + ty) * 32 + tx);
        float4 gG = __ldcg(Gp + (size_t)(2 * HH + hc0 + ty) * 32 + tx);
        float4 gO = __ldcg(Gp + (size_t)(3 * HH + hc0 + ty) * 32 + tx);
        float gi[4] = {gI.x, gI.y, gI.z, gI.w};
        float gf[4] = {gF.x, gF.y, gF.z, gF.w};
        float gg[4] = {gG.x, gG.y, gG.z, gG.w};
        float go[4] = {gO.x, gO.y, gO.z, gO.w};
        float hv[4];
#pragma unroll
        for (int bi = 0; bi < 4; bi++) {
            float iv = sigmoidf_(gi[bi] + acc[bi][0]);
            float fv = sigmoidf_(gf[bi] + acc[bi][1]);
            float gv = tanhf(gg[bi] + acc[bi][2]);
            float ov = sigmoidf_(go[bi] + acc[bi][3]);
            c[bi] = fv * c[bi] + iv * gv;
            hv[bi] = ov * tanhf(c[bi]);
        }
        float4 hq = make_float4(hv[0], hv[1], hv[2], hv[3]);
        *(float4*)(g_h + ((size_t)(dir * TT + t) * HH + hc0 + ty) * BB + tx * 4) = hq;

        grid_sync();
    }
}

// ---------------- kernel 3: emissions = concat(hf,hb) @ lin_W^T + lin_b ----------------
__global__ void __launch_bounds__(128) emissions_k(
    const float* __restrict__ linW, const float* __restrict__ linb)
{
    __shared__ float w_s[NK * 2 * HH];  // 7168 floats
    const int t = blockIdx.x;
    const int tid = threadIdx.x;  // = b
    for (int i = tid; i < NK * 2 * HH; i += 128) w_s[i] = linW[i];
    __syncthreads();

    float acc[NK];
#pragma unroll
    for (int k = 0; k < NK; k++) acc[k] = 0.0f;

    for (int dir = 0; dir < 2; dir++) {
        const float* hp = g_h + (size_t)(dir * TT + t) * HH * BB;
        const int wo = dir * HH;
#pragma unroll 4
        for (int cc = 0; cc < HH; cc++) {
            float h = hp[cc * BB + tid];
#pragma unroll
            for (int k = 0; k < NK; k++) acc[k] += h * w_s[k * 1024 + wo + cc];
        }
    }
#pragma unroll
    for (int k = 0; k < NK; k++)
        g_em[((size_t)t * BB + tid) * NK + k] = acc[k] + linb[k];
}

// ---------------- kernel 4: CRF score + forward algorithm (1 warp per batch elt) -------
__global__ void __launch_bounds__(32) crf_k(
    const int* __restrict__ labels, const float* __restrict__ trans,
    const float* __restrict__ startT, const float* __restrict__ endT)
{
    const int b = blockIdx.x;
    const int lane = threadIdx.x;

    // gold-path score (strided over t, warp reduce)
    float sc = 0.0f;
    for (int t = lane; t < TT; t += 32) {
        int lt = labels[b * TT + t];
        sc += g_em[((size_t)t * BB + b) * NK + lt];
        if (t < TT - 1) sc += trans[lt * NK + labels[b * TT + t + 1]];
    }
#pragma unroll
    for (int o = 16; o; o >>= 1) sc += __shfl_down_sync(0xffffffffu, sc, o);

    // forward recursion: lane k' owns alpha[k'] (lanes >=7 mirror k'=0, unused)
    const int k = (lane < NK) ? lane : 0;
    float tr[NK];
#pragma unroll
    for (int j = 0; j < NK; j++) tr[j] = trans[j * NK + k];

    float alpha = startT[k] + g_em[(size_t)b * NK + k];  // t = 0
    for (int t = 1; t < TT; t++) {
        float v[NK];
        float m = -3.0e38f;
#pragma unroll
        for (int j = 0; j < NK; j++) {
            v[j] = __shfl_sync(0xffffffffu, alpha, j) + tr[j];
            m = fmaxf(m, v[j]);
        }
        float ssum = 0.0f;
#pragma unroll
        for (int j = 0; j < NK; j++) ssum += expf(v[j] - m);
        alpha = m + logf(ssum) + g_em[((size_t)t * BB + b) * NK + k];
    }
    float av = alpha + endT[k];
    float mm = av;
#pragma unroll
    for (int j = 0; j < NK; j++) mm = fmaxf(mm, __shfl_sync(0xffffffffu, av, j));
    float e = (lane < NK) ? expf(av - mm) : 0.0f;
#pragma unroll
    for (int o = 16; o; o >>= 1) e += __shfl_down_sync(0xffffffffu, e, o);

    if (lane == 0) {
        float logZ = mm + logf(e);
        float score = sc + startT[labels[b * TT]] + endT[labels[b * TT + TT - 1]];
        g_lossB[b] = score - logZ;
    }
}

// ---------------- kernel 5: deterministic final reduce ----------------
__global__ void __launch_bounds__(128) final_reduce(float* out)
{
    __shared__ float s[128];
    s[threadIdx.x] = g_lossB[threadIdx.x];
    __syncthreads();
    for (int o = 64; o; o >>= 1) {
        if (threadIdx.x < o) s[threadIdx.x] += s[threadIdx.x + o];
        __syncthreads();
    }
    if (threadIdx.x == 0) out[0] = -s[0];
}

// ---------------- launch ----------------
extern "C" void kernel_launch(void* const* d_in, const int* in_sizes, int n_in,
                              void* d_out, int out_size)
{
    const int*   inputData = (const int*)d_in[0];
    const int*   labels    = (const int*)d_in[1];
    const float* embed     = (const float*)d_in[2];
    const float* WihF = (const float*)d_in[3];
    const float* WhhF = (const float*)d_in[4];
    const float* bihF = (const float*)d_in[5];
    const float* bhhF = (const float*)d_in[6];
    const float* WihB = (const float*)d_in[7];
    const float* WhhB = (const float*)d_in[8];
    const float* bihB = (const float*)d_in[9];
    const float* bhhB = (const float*)d_in[10];
    const float* linW = (const float*)d_in[11];
    const float* linb = (const float*)d_in[12];
    const float* trans = (const float*)d_in[13];
    const float* startT = (const float*)d_in[14];
    const float* endT   = (const float*)d_in[15];

    input_gemm<<<dim3(16, 256, 2), 256>>>(inputData, embed, WihF, WihB, bihF, bhhF, bihB, bhhB);

    cudaFuncSetAttribute(recurrent, cudaFuncAttributeMaxDynamicSharedMemorySize, 131072);
    recurrent<<<NCTAS, 256, 131072>>>(WhhF, WhhB);

    emissions_k<<<TT, 128>>>(linW, linb);
    crf_k<<<BB, 32>>>(labels, trans, startT, endT);
    final_reduce<<<1, 128>>>((float*)d_out);
}

// round 8
// speedup vs baseline: 2.5403x; 2.5403x over previous
#include <cuda_runtime.h>
#include <cuda_bf16.h>
#include <math.h>

#define TT 256
#define BB 128
#define EE 256
#define HH 512
#define G4 2048
#define NK 7
#define NCTAS 128

#define SPH 520
#define SPW 520
#define SP2 264

__device__ float g_G[134217728];
__device__ __nv_bfloat16 g_hb[33554432];
__device__ float g_em[229376];
__device__ float g_lossB[BB];
__device__ unsigned g_bar_cnt;
__device__ unsigned g_bar_gen;

__device__ __forceinline__ void grid_sync() {
    __threadfence();
    __syncthreads();
    if (threadIdx.x == 0) {
        unsigned a = atomicAdd(&g_bar_cnt, 1u) + 1u;
        unsigned need = (a - 1u) / NCTAS + 1u;
        if (a % NCTAS == 0u) {
            atomicExch(&g_bar_gen, need);
        } else {
            while (atomicAdd(&g_bar_gen, 0u) < need) { __nanosleep(64); }
        }
        __threadfence();
    }
    __syncthreads();
}

__device__ __forceinline__ float sigmoidf_(float x) { return 1.0f / (1.0f + expf(-x)); }

__device__ __forceinline__ unsigned smem_u32(const void* p) {
    return (unsigned)__cvta_generic_to_shared(p);
}

__device__ __forceinline__ void ldsm4(unsigned addr, unsigned* r) {
    asm volatile("ldmatrix.sync.aligned.m8n8.x4.shared.b16 {%0,%1,%2,%3}, [%4];"
                 : "=r"(r[0]), "=r"(r[1]), "=r"(r[2]), "=r"(r[3]) : "r"(addr));
}

__device__ __forceinline__ void mma_bf16(float* c, const unsigned* a, unsigned b0, unsigned b1) {
    asm volatile(
        "mma.sync.aligned.m16n8k16.row.col.f32.bf16.bf16.f32 "
        "{%0,%1,%2,%3},{%4,%5,%6,%7},{%8,%9},{%0,%1,%2,%3};"
        : "+f"(c[0]), "+f"(c[1]), "+f"(c[2]), "+f"(c[3])
        : "r"(a[0]), "r"(a[1]), "r"(a[2]), "r"(a[3]), "r"(b0), "r"(b1));
}

__device__ __forceinline__ void cvt4_bf16(__nv_bfloat16* d, float4 v) {
    d[0] = __float2bfloat16_rn(v.x);
    d[1] = __float2bfloat16_rn(v.y);
    d[2] = __float2bfloat16_rn(v.z);
    d[3] = __float2bfloat16_rn(v.w);
}

// lane-pattern address helpers (row-major K-major tile, stride in halves)
__device__ __forceinline__ unsigned ldsmA_off(int warp, int lane, int stride) {
    int ar = warp * 16 + (lane & 15);
    int ak = (lane >> 4) * 8;
    return (unsigned)((ar * stride + ak) * 2);
}
__device__ __forceinline__ unsigned ldsmB_off(int lane, int stride) {
    int br = ((lane >> 4) << 3) + (lane & 7);
    int bk = ((lane >> 3) & 1) * 8;
    return (unsigned)((br * stride + bk) * 2);
}

// =============== kernel 1: embedding gather + input GEMM (bf16 mma) + bias ===========
__global__ void __launch_bounds__(256, 1) input_gemm(
    const int* __restrict__ inputData, const float* __restrict__ embed,
    const float* __restrict__ WihF, const float* __restrict__ WihB,
    const float* __restrict__ bihF, const float* __restrict__ bhhF,
    const float* __restrict__ bihB, const float* __restrict__ bhhB)
{
    extern __shared__ __align__(16) char ig_smem[];
    __nv_bfloat16* ig_As = (__nv_bfloat16*)ig_smem;
    __nv_bfloat16* ig_Xs = (__nv_bfloat16*)(ig_smem + 128 * SP2 * 2);
    __shared__ int ig_rows[128];

    const int dir = blockIdx.z;
    const int t   = blockIdx.y;
    const int j0  = blockIdx.x * 128;
    const float* __restrict__ Wih = dir ? WihB : WihF;
    const float* __restrict__ bih = dir ? bihB : bihF;
    const float* __restrict__ bhh = dir ? bhhB : bhhF;

    const int ig_tid  = threadIdx.x;
    const int ig_warp = ig_tid >> 5;
    const int ig_lane = ig_tid & 31;

    if (ig_tid < 128) ig_rows[ig_tid] = inputData[t * BB + ig_tid];
    __syncthreads();

    for (int wi = ig_tid; wi < 128 * 64; wi += 256) {
        int wr = wi >> 6;
        int wk = (wi & 63) * 4;
        float4 wv = *(const float4*)(Wih + (size_t)(j0 + wr) * EE + wk);
        cvt4_bf16(ig_As + wr * SP2 + wk, wv);
    }
    for (int xi = ig_tid; xi < 128 * 64; xi += 256) {
        int xb = xi >> 6;
        int xk = (xi & 63) * 4;
        float4 xv = *(const float4*)(embed + (size_t)ig_rows[xb] * EE + xk);
        cvt4_bf16(ig_Xs + xb * SP2 + xk, xv);
    }
    __syncthreads();

    const unsigned ig_aaddr = smem_u32(ig_As) + ldsmA_off(ig_warp, ig_lane, SP2);
    const unsigned ig_xaddr = smem_u32(ig_Xs) + ldsmB_off(ig_lane, SP2);

    float ig_acc[16][4];
#pragma unroll
    for (int ci = 0; ci < 16; ci++) {
#pragma unroll
        for (int cj = 0; cj < 4; cj++) ig_acc[ci][cj] = 0.0f;
    }

#pragma unroll
    for (int ks = 0; ks < 16; ks++) {
        unsigned ig_af[4];
        ldsm4(ig_aaddr + ks * 32, ig_af);
#pragma unroll
        for (int bt = 0; bt < 8; bt++) {
            unsigned ig_xf[4];
            ldsm4(ig_xaddr + bt * (16 * SP2 * 2) + ks * 32, ig_xf);
            mma_bf16(ig_acc[2 * bt], ig_af, ig_xf[0], ig_xf[1]);
            mma_bf16(ig_acc[2 * bt + 1], ig_af, ig_xf[2], ig_xf[3]);
        }
    }

    const int ig_q = ig_lane & 3;
    const int ig_rq = ig_lane >> 2;
    const int ig_j = j0 + ig_warp * 16 + ig_rq;
    const float ig_bias0 = bih[ig_j] + bhh[ig_j];
    const float ig_bias1 = bih[ig_j + 8] + bhh[ig_j + 8];
    const size_t ig_base0 = ((size_t)(dir * TT + t) * G4 + ig_j) * BB;
    const size_t ig_base1 = ig_base0 + 8 * BB;
#pragma unroll
    for (int nt = 0; nt < 16; nt++) {
        int ob = nt * 8 + 2 * ig_q;
        *(float2*)(g_G + ig_base0 + ob) = make_float2(ig_acc[nt][0] + ig_bias0, ig_acc[nt][1] + ig_bias0);
        *(float2*)(g_G + ig_base1 + ob) = make_float2(ig_acc[nt][2] + ig_bias1, ig_acc[nt][3] + ig_bias1);
    }
}

// =============== kernel 2: persistent BiLSTM recurrence (bf16 mma) ===================
__global__ void __launch_bounds__(256, 1) recurrent(
    const float* __restrict__ WhhF, const float* __restrict__ WhhB)
{
    extern __shared__ __align__(16) char rc_smem[];
    __nv_bfloat16* rc_hs = (__nv_bfloat16*)rc_smem;
    __nv_bfloat16* rc_ws = (__nv_bfloat16*)(rc_smem + 128 * SPH * 2);

    const int rc_tid  = threadIdx.x;
    const int rc_warp = rc_tid >> 5;
    const int rc_lane = rc_tid & 31;
    const int rc_bid  = blockIdx.x;
    const int dir     = rc_bid >> 6;
    const int hc0     = (rc_bid & 63) * 8;
    const float* __restrict__ Whh = dir ? WhhB : WhhF;

    for (int wi = rc_tid; wi < 32 * 512; wi += 256) {
        int wrow = wi >> 9;
        int wk = wi & 511;
        int wj = (wrow >> 3) * HH + hc0 + (wrow & 7);
        rc_ws[wrow * SPW + wk] = __float2bfloat16_rn(Whh[(size_t)wj * HH + wk]);
    }
    __syncthreads();

    const unsigned rc_haddr = smem_u32(rc_hs) + ldsmA_off(rc_warp, rc_lane, SPH);
    const unsigned rc_w0 = smem_u32(rc_ws) + ldsmB_off(rc_lane, SPW);
    const unsigned rc_w1 = rc_w0 + 16 * SPW * 2;

    const int rc_q  = rc_lane & 3;
    const int rc_rq = rc_lane >> 2;
    const int rc_bl = rc_warp * 16 + rc_rq;

    float rc_c[4] = {0.f, 0.f, 0.f, 0.f};

    for (int s = 0; s < TT; s++) {
        const int t = dir ? (TT - 1 - s) : s;
        float rc_acc[4][4];
#pragma unroll
        for (int gi = 0; gi < 4; gi++) {
#pragma unroll
            for (int pi = 0; pi < 4; pi++) rc_acc[gi][pi] = 0.0f;
        }

        if (s > 0) {
            const int tp = dir ? (t + 1) : (t - 1);
            const uint4* rc_src = (const uint4*)(g_hb + (size_t)(dir * TT + tp) * BB * HH);
            __syncthreads();
#pragma unroll
            for (int li = 0; li < 32; li++) {
                int lv = li * 256 + rc_tid;
                int lb = lv >> 6;
                int lu = lv & 63;
                uint4 hvv = __ldcg(rc_src + lv);
                *(uint4*)(rc_hs + lb * SPH + lu * 8) = hvv;
            }
            __syncthreads();
#pragma unroll 4
            for (int ks = 0; ks < 32; ks++) {
                unsigned rc_af[4];
                unsigned rc_bf[4];
                unsigned rc_cf[4];
                ldsm4(rc_haddr + ks * 32, rc_af);
                ldsm4(rc_w0 + ks * 32, rc_bf);
                ldsm4(rc_w1 + ks * 32, rc_cf);
                mma_bf16(rc_acc[0], rc_af, rc_bf[0], rc_bf[1]);
                mma_bf16(rc_acc[1], rc_af, rc_bf[2], rc_bf[3]);
                mma_bf16(rc_acc[2], rc_af, rc_cf[0], rc_cf[1]);
                mma_bf16(rc_acc[3], rc_af, rc_cf[2], rc_cf[3]);
            }
        }

        const float* rc_Gp = g_G + (size_t)(dir * TT + t) * G4 * BB;
        float rc_h[4];
#pragma unroll
        for (int pp = 0; pp < 4; pp++) {
            int pb = rc_bl + (pp >> 1) * 8;
            int ph = 2 * rc_q + (pp & 1);
            float pgi = rc_Gp[(size_t)(0 * HH + hc0 + ph) * BB + pb] + rc_acc[0][pp];
            float pgf = rc_Gp[(size_t)(1 * HH + hc0 + ph) * BB + pb] + rc_acc[1][pp];
            float pgg = rc_Gp[(size_t)(2 * HH + hc0 + ph) * BB + pb] + rc_acc[2][pp];
            float pgo = rc_Gp[(size_t)(3 * HH + hc0 + ph) * BB + pb] + rc_acc[3][pp];
            float piv = sigmoidf_(pgi);
            float pfv = sigmoidf_(pgf);
            float pgv = tanhf(pgg);
            float pov = sigmoidf_(pgo);
            rc_c[pp] = pfv * rc_c[pp] + piv * pgv;
            rc_h[pp] = pov * tanhf(rc_c[pp]);
        }
        __nv_bfloat16* rc_dst = g_hb + ((size_t)(dir * TT + t) * BB + rc_bl) * HH + hc0 + 2 * rc_q;
        *(__nv_bfloat162*)rc_dst = __nv_bfloat162(__float2bfloat16_rn(rc_h[0]), __float2bfloat16_rn(rc_h[1]));
        *(__nv_bfloat162*)(rc_dst + 8 * HH) = __nv_bfloat162(__float2bfloat16_rn(rc_h[2]), __float2bfloat16_rn(rc_h[3]));

        grid_sync();
    }
}

// =============== kernel 3: emissions, warp per (t, b) ================================
__global__ void __launch_bounds__(128) emissions_k(
    const float* __restrict__ linW, const float* __restrict__ linb)
{
    const int em_t = blockIdx.y;
    const int em_b = blockIdx.x * 4 + (threadIdx.x >> 5);
    const int em_lane = threadIdx.x & 31;

    float em_acc[NK];
#pragma unroll
    for (int kc = 0; kc < NK; kc++) em_acc[kc] = 0.0f;

#pragma unroll
    for (int dd = 0; dd < 2; dd++) {
        const __nv_bfloat162* em_hp = (const __nv_bfloat162*)(g_hb + ((size_t)(dd * TT + em_t) * BB + em_b) * HH);
        const int em_wo = dd * HH;
#pragma unroll
        for (int it = 0; it < 8; it++) {
            int em_k = it * 64 + em_lane * 2;
            __nv_bfloat162 em_hv = em_hp[it * 32 + em_lane];
            float em_hx = __bfloat162float(em_hv.x);
            float em_hy = __bfloat162float(em_hv.y);
#pragma unroll
            for (int kc = 0; kc < NK; kc++) {
                const float* em_wr = linW + kc * (2 * HH) + em_wo + em_k;
                em_acc[kc] += em_hx * __ldg(em_wr) + em_hy * __ldg(em_wr + 1);
            }
        }
    }
#pragma unroll
    for (int kc = 0; kc < NK; kc++) {
#pragma unroll
        for (int o = 16; o; o >>= 1) em_acc[kc] += __shfl_xor_sync(0xffffffffu, em_acc[kc], o);
    }
    if (em_lane == 0) {
#pragma unroll
        for (int kc = 0; kc < NK; kc++) g_em[((size_t)em_t * BB + em_b) * NK + kc] = em_acc[kc] + linb[kc];
    }
}

// =============== kernel 4: CRF score + forward algorithm =============================
__global__ void __launch_bounds__(32) crf_k(
    const int* __restrict__ labels, const float* __restrict__ trans,
    const float* __restrict__ startT, const float* __restrict__ endT)
{
    const int cb = blockIdx.x;
    const int cl = threadIdx.x;

    float csc = 0.0f;
    for (int ct = cl; ct < TT; ct += 32) {
        int clt = labels[cb * TT + ct];
        csc += g_em[((size_t)ct * BB + cb) * NK + clt];
        if (ct < TT - 1) csc += trans[clt * NK + labels[cb * TT + ct + 1]];
    }
#pragma unroll
    for (int o = 16; o; o >>= 1) csc += __shfl_down_sync(0xffffffffu, csc, o);

    const int ck = (cl < NK) ? cl : 0;
    float ctr[NK];
#pragma unroll
    for (int cj = 0; cj < NK; cj++) ctr[cj] = trans[cj * NK + ck];

    float calpha = startT[ck] + g_em[(size_t)cb * NK + ck];
    for (int ct = 1; ct < TT; ct++) {
        float cv[NK];
        float cm = -3.0e38f;
#pragma unroll
        for (int cj = 0; cj < NK; cj++) {
            cv[cj] = __shfl_sync(0xffffffffu, calpha, cj) + ctr[cj];
            cm = fmaxf(cm, cv[cj]);
        }
        float cs = 0.0f;
#pragma unroll
        for (int cj = 0; cj < NK; cj++) cs += expf(cv[cj] - cm);
        calpha = cm + logf(cs) + g_em[((size_t)ct * BB + cb) * NK + ck];
    }
    float cav = calpha + endT[ck];
    float cmm = cav;
#pragma unroll
    for (int cj = 0; cj < NK; cj++) cmm = fmaxf(cmm, __shfl_sync(0xffffffffu, cav, cj));
    float ce = (cl < NK) ? expf(cav - cmm) : 0.0f;
#pragma unroll
    for (int o = 16; o; o >>= 1) ce += __shfl_down_sync(0xffffffffu, ce, o);

    if (cl == 0) {
        float clogZ = cmm + logf(ce);
        float cscore = csc + startT[labels[cb * TT]] + endT[labels[cb * TT + TT - 1]];
        g_lossB[cb] = cscore - clogZ;
    }
}

// =============== kernel 5: deterministic final reduce ================================
__global__ void __launch_bounds__(128) final_reduce(float* out)
{
    __shared__ float fr_s[128];
    fr_s[threadIdx.x] = g_lossB[threadIdx.x];
    __syncthreads();
    for (int o = 64; o; o >>= 1) {
        if (threadIdx.x < o) fr_s[threadIdx.x] += fr_s[threadIdx.x + o];
        __syncthreads();
    }
    if (threadIdx.x == 0) out[0] = -fr_s[0];
}

// =============== launch ==============================================================
extern "C" void kernel_launch(void* const* d_in, const int* in_sizes, int n_in,
                              void* d_out, int out_size)
{
    const int*   inputData = (const int*)d_in[0];
    const int*   labels    = (const int*)d_in[1];
    const float* embed     = (const float*)d_in[2];
    const float* WihF = (const float*)d_in[3];
    const float* WhhF = (const float*)d_in[4];
    const float* bihF = (const float*)d_in[5];
    const float* bhhF = (const float*)d_in[6];
    const float* WihB = (const float*)d_in[7];
    const float* WhhB = (const float*)d_in[8];
    const float* bihB = (const float*)d_in[9];
    const float* bhhB = (const float*)d_in[10];
    const float* linW = (const float*)d_in[11];
    const float* linb = (const float*)d_in[12];
    const float* trans = (const float*)d_in[13];
    const float* startT = (const float*)d_in[14];
    const float* endT   = (const float*)d_in[15];

    cudaFuncSetAttribute(input_gemm, cudaFuncAttributeMaxDynamicSharedMemorySize, 2 * 128 * SP2 * 2);
    cudaFuncSetAttribute(recurrent, cudaFuncAttributeMaxDynamicSharedMemorySize, 128 * SPH * 2 + 32 * SPW * 2);

    input_gemm<<<dim3(16, 256, 2), 256, 2 * 128 * SP2 * 2>>>(inputData, embed, WihF, WihB, bihF, bhhF, bihB, bhhB);

    recurrent<<<NCTAS, 256, 128 * SPH * 2 + 32 * SPW * 2>>>(WhhF, WhhB);

    emissions_k<<<dim3(32, TT), 128>>>(linW, linb);
    crf_k<<<BB, 32>>>(labels, trans, startT, endT);
    final_reduce<<<1, 128>>>((float*)d_out);
}

// round 9
// speedup vs baseline: 2.7539x; 1.0841x over previous
#include <cuda_runtime.h>
#include <cuda_bf16.h>
#include <math.h>

#define TT 256
#define BB 128
#define EE 256
#define HH 512
#define G4 2048
#define NK 7
#define NCTAS 128

#define SPH 520
#define SPW 520
#define SP2 264

__device__ float g_G[134217728];
__device__ __nv_bfloat16 g_hb[33554432];
__device__ float g_em[229376];
__device__ float g_lossB[BB];
__device__ unsigned g_bar_cnt;
__device__ unsigned g_bar_gen;

__device__ __forceinline__ void grid_sync_fast() {
    __syncthreads();
    if (threadIdx.x == 0) {
        unsigned bs_a;
        asm volatile("atom.add.release.gpu.u32 %0, [%1], 1;"
                     : "=r"(bs_a) : "l"(&g_bar_cnt) : "memory");
        bs_a += 1u;
        unsigned bs_need = (bs_a - 1u) / NCTAS + 1u;
        if (bs_a % NCTAS == 0u) {
            asm volatile("st.release.gpu.u32 [%0], %1;"
                         :: "l"(&g_bar_gen), "r"(bs_need) : "memory");
        } else {
            unsigned bs_g = 0u;
            do {
                asm volatile("ld.acquire.gpu.u32 %0, [%1];"
                             : "=r"(bs_g) : "l"(&g_bar_gen) : "memory");
            } while (bs_g < bs_need);
        }
    }
    __syncthreads();
}

__device__ __forceinline__ float sigmoidf_(float x) { return 1.0f / (1.0f + expf(-x)); }

__device__ __forceinline__ unsigned smem_u32(const void* p) {
    return (unsigned)__cvta_generic_to_shared(p);
}

__device__ __forceinline__ void ldsm4(unsigned addr, unsigned* r) {
    asm volatile("ldmatrix.sync.aligned.m8n8.x4.shared.b16 {%0,%1,%2,%3}, [%4];"
                 : "=r"(r[0]), "=r"(r[1]), "=r"(r[2]), "=r"(r[3]) : "r"(addr));
}

__device__ __forceinline__ void mma_bf16(float* c, const unsigned* a, unsigned b0, unsigned b1) {
    asm volatile(
        "mma.sync.aligned.m16n8k16.row.col.f32.bf16.bf16.f32 "
        "{%0,%1,%2,%3},{%4,%5,%6,%7},{%8,%9},{%0,%1,%2,%3};"
        : "+f"(c[0]), "+f"(c[1]), "+f"(c[2]), "+f"(c[3])
        : "r"(a[0]), "r"(a[1]), "r"(a[2]), "r"(a[3]), "r"(b0), "r"(b1));
}

__device__ __forceinline__ void cp_async16(unsigned saddr, const void* gaddr) {
    asm volatile("cp.async.cg.shared.global [%0], [%1], 16;" :: "r"(saddr), "l"(gaddr));
}
__device__ __forceinline__ void cp_commit() { asm volatile("cp.async.commit_group;"); }
__device__ __forceinline__ void cp_wait1() { asm volatile("cp.async.wait_group 1;"); }
__device__ __forceinline__ void cp_wait0() { asm volatile("cp.async.wait_group 0;"); }

__device__ __forceinline__ void cvt4_bf16(__nv_bfloat16* d, float4 v) {
    d[0] = __float2bfloat16_rn(v.x);
    d[1] = __float2bfloat16_rn(v.y);
    d[2] = __float2bfloat16_rn(v.z);
    d[3] = __float2bfloat16_rn(v.w);
}

__device__ __forceinline__ unsigned ldsmA_off(int warp, int lane, int stride) {
    int ar = warp * 16 + (lane & 15);
    int ak = (lane >> 4) * 8;
    return (unsigned)((ar * stride + ak) * 2);
}
__device__ __forceinline__ unsigned ldsmB_off(int lane, int stride) {
    int br = ((lane >> 4) << 3) + (lane & 7);
    int bk = ((lane >> 3) & 1) * 8;
    return (unsigned)((br * stride + bk) * 2);
}

// =============== kernel 1: embedding gather + input GEMM (bf16 mma) + bias ===========
// 2 time-steps per block: Wih smem tile loaded once, reused.
__global__ void __launch_bounds__(256, 1) input_gemm(
    const int* __restrict__ inputData, const float* __restrict__ embed,
    const float* __restrict__ WihF, const float* __restrict__ WihB,
    const float* __restrict__ bihF, const float* __restrict__ bhhF,
    const float* __restrict__ bihB, const float* __restrict__ bhhB)
{
    extern __shared__ __align__(16) char ig_smem[];
    __nv_bfloat16* ig_As = (__nv_bfloat16*)ig_smem;
    __nv_bfloat16* ig_Xs = (__nv_bfloat16*)(ig_smem + 128 * SP2 * 2);
    __shared__ int ig_rows[128];

    const int dir = blockIdx.z;
    const int t0  = blockIdx.y * 2;
    const int j0  = blockIdx.x * 128;
    const float* __restrict__ Wih = dir ? WihB : WihF;
    const float* __restrict__ bih = dir ? bihB : bihF;
    const float* __restrict__ bhh = dir ? bhhB : bhhF;

    const int ig_tid  = threadIdx.x;
    const int ig_warp = ig_tid >> 5;
    const int ig_lane = ig_tid & 31;

    for (int wi = ig_tid; wi < 128 * 64; wi += 256) {
        int wr = wi >> 6;
        int wk = (wi & 63) * 4;
        float4 wv = *(const float4*)(Wih + (size_t)(j0 + wr) * EE + wk);
        cvt4_bf16(ig_As + wr * SP2 + wk, wv);
    }

    const unsigned ig_aaddr = smem_u32(ig_As) + ldsmA_off(ig_warp, ig_lane, SP2);
    const unsigned ig_xaddr = smem_u32(ig_Xs) + ldsmB_off(ig_lane, SP2);

    const int ig_q = ig_lane & 3;
    const int ig_rq = ig_lane >> 2;
    const int ig_j = j0 + ig_warp * 16 + ig_rq;
    const float ig_bias0 = bih[ig_j] + bhh[ig_j];
    const float ig_bias1 = bih[ig_j + 8] + bhh[ig_j + 8];

    for (int tt = 0; tt < 2; tt++) {
        const int t = t0 + tt;
        if (ig_tid < 128) ig_rows[ig_tid] = inputData[t * BB + ig_tid];
        __syncthreads();

        for (int xi = ig_tid; xi < 128 * 64; xi += 256) {
            int xb = xi >> 6;
            int xk = (xi & 63) * 4;
            float4 xv = *(const float4*)(embed + (size_t)ig_rows[xb] * EE + xk);
            cvt4_bf16(ig_Xs + xb * SP2 + xk, xv);
        }
        __syncthreads();

        float ig_acc[16][4];
#pragma unroll
        for (int ci = 0; ci < 16; ci++) {
#pragma unroll
            for (int cj = 0; cj < 4; cj++) ig_acc[ci][cj] = 0.0f;
        }

#pragma unroll
        for (int ks = 0; ks < 16; ks++) {
            unsigned ig_af[4];
            ldsm4(ig_aaddr + ks * 32, ig_af);
#pragma unroll
            for (int bt = 0; bt < 8; bt++) {
                unsigned ig_xf[4];
                ldsm4(ig_xaddr + bt * (16 * SP2 * 2) + ks * 32, ig_xf);
                mma_bf16(ig_acc[2 * bt], ig_af, ig_xf[0], ig_xf[1]);
                mma_bf16(ig_acc[2 * bt + 1], ig_af, ig_xf[2], ig_xf[3]);
            }
        }

        const size_t ig_base0 = ((size_t)(dir * TT + t) * G4 + ig_j) * BB;
        const size_t ig_base1 = ig_base0 + 8 * BB;
#pragma unroll
        for (int nt = 0; nt < 16; nt++) {
            int ob = nt * 8 + 2 * ig_q;
            *(float2*)(g_G + ig_base0 + ob) = make_float2(ig_acc[nt][0] + ig_bias0, ig_acc[nt][1] + ig_bias0);
            *(float2*)(g_G + ig_base1 + ob) = make_float2(ig_acc[nt][2] + ig_bias1, ig_acc[nt][3] + ig_bias1);
        }
        __syncthreads();
    }
}

// =============== kernel 2: persistent BiLSTM recurrence (bf16 mma, pipelined) ========
__global__ void __launch_bounds__(256, 1) recurrent(
    const float* __restrict__ WhhF, const float* __restrict__ WhhB)
{
    extern __shared__ __align__(16) char rc_smem[];
    __nv_bfloat16* rc_hs = (__nv_bfloat16*)rc_smem;
    __nv_bfloat16* rc_ws = (__nv_bfloat16*)(rc_smem + 128 * SPH * 2);

    const int rc_tid  = threadIdx.x;
    const int rc_warp = rc_tid >> 5;
    const int rc_lane = rc_tid & 31;
    const int rc_bid  = blockIdx.x;
    const int dir     = rc_bid >> 6;
    const int hc0     = (rc_bid & 63) * 8;
    const float* __restrict__ Whh = dir ? WhhB : WhhF;

    for (int wi = rc_tid; wi < 32 * 512; wi += 256) {
        int wrow = wi >> 9;
        int wk = wi & 511;
        int wj = (wrow >> 3) * HH + hc0 + (wrow & 7);
        rc_ws[wrow * SPW + wk] = __float2bfloat16_rn(Whh[(size_t)wj * HH + wk]);
    }
    __syncthreads();

    const unsigned rc_hbase = smem_u32(rc_hs);
    const unsigned rc_haddr = rc_hbase + ldsmA_off(rc_warp, rc_lane, SPH);
    const unsigned rc_w0 = smem_u32(rc_ws) + ldsmB_off(rc_lane, SPW);
    const unsigned rc_w1 = rc_w0 + 16 * SPW * 2;

    const int rc_q  = rc_lane & 3;
    const int rc_rq = rc_lane >> 2;
    const int rc_bl = rc_warp * 16 + rc_rq;

    float rc_c[4] = {0.f, 0.f, 0.f, 0.f};

    for (int s = 0; s < TT; s++) {
        const int t = dir ? (TT - 1 - s) : s;

        // prefetch gate preactivations (independent of h) to hide DRAM latency
        const float* rc_Gp = g_G + (size_t)(dir * TT + t) * G4 * BB;
        float rc_pg[4][4];
#pragma unroll
        for (int gi = 0; gi < 4; gi++) {
#pragma unroll
            for (int pp = 0; pp < 4; pp++) {
                int qb = rc_bl + (pp >> 1) * 8;
                int qh = 2 * rc_q + (pp & 1);
                rc_pg[gi][pp] = __ldcg(rc_Gp + (size_t)(gi * HH + hc0 + qh) * BB + qb);
            }
        }

        float rc_acc[4][4];
#pragma unroll
        for (int gi = 0; gi < 4; gi++) {
#pragma unroll
            for (int pi = 0; pi < 4; pi++) rc_acc[gi][pi] = 0.0f;
        }

        if (s > 0) {
            const int tp = dir ? (t + 1) : (t - 1);
            const uint4* rc_src = (const uint4*)(g_hb + (size_t)(dir * TT + tp) * BB * HH);
            // chunk 0: k 0..255 ; chunk 1: k 256..511 (cp.async, 2 commit groups)
#pragma unroll
            for (int li = 0; li < 16; li++) {
                int lv = li * 256 + rc_tid;
                int lrow = lv >> 5;
                int lu = lv & 31;
                unsigned lsa = rc_hbase + (unsigned)((lrow * SPH + lu * 8) * 2);
                cp_async16(lsa, (const void*)(rc_src + lrow * 64 + lu));
            }
            cp_commit();
#pragma unroll
            for (int li = 0; li < 16; li++) {
                int lv = li * 256 + rc_tid;
                int lrow = lv >> 5;
                int lu = (lv & 31) + 32;
                unsigned lsa = rc_hbase + (unsigned)((lrow * SPH + lu * 8) * 2);
                cp_async16(lsa, (const void*)(rc_src + lrow * 64 + lu));
            }
            cp_commit();
            cp_wait1();
            __syncthreads();
#pragma unroll 4
            for (int ks = 0; ks < 16; ks++) {
                unsigned rc_af[4];
                unsigned rc_bf[4];
                unsigned rc_cf[4];
                ldsm4(rc_haddr + ks * 32, rc_af);
                ldsm4(rc_w0 + ks * 32, rc_bf);
                ldsm4(rc_w1 + ks * 32, rc_cf);
                mma_bf16(rc_acc[0], rc_af, rc_bf[0], rc_bf[1]);
                mma_bf16(rc_acc[1], rc_af, rc_bf[2], rc_bf[3]);
                mma_bf16(rc_acc[2], rc_af, rc_cf[0], rc_cf[1]);
                mma_bf16(rc_acc[3], rc_af, rc_cf[2], rc_cf[3]);
            }
            cp_wait0();
            __syncthreads();
#pragma unroll 4
            for (int ks = 16; ks < 32; ks++) {
                unsigned rc_af[4];
                unsigned rc_bf[4];
                unsigned rc_cf[4];
                ldsm4(rc_haddr + ks * 32, rc_af);
                ldsm4(rc_w0 + ks * 32, rc_bf);
                ldsm4(rc_w1 + ks * 32, rc_cf);
                mma_bf16(rc_acc[0], rc_af, rc_bf[0], rc_bf[1]);
                mma_bf16(rc_acc[1], rc_af, rc_bf[2], rc_bf[3]);
                mma_bf16(rc_acc[2], rc_af, rc_cf[0], rc_cf[1]);
                mma_bf16(rc_acc[3], rc_af, rc_cf[2], rc_cf[3]);
            }
        }

        float rc_h[4];
#pragma unroll
        for (int pp = 0; pp < 4; pp++) {
            float pgi = rc_pg[0][pp] + rc_acc[0][pp];
            float pgf = rc_pg[1][pp] + rc_acc[1][pp];
            float pgg = rc_pg[2][pp] + rc_acc[2][pp];
            float pgo = rc_pg[3][pp] + rc_acc[3][pp];
            float piv = sigmoidf_(pgi);
            float pfv = sigmoidf_(pgf);
            float pgv = tanhf(pgg);
            float pov = sigmoidf_(pgo);
            rc_c[pp] = pfv * rc_c[pp] + piv * pgv;
            rc_h[pp] = pov * tanhf(rc_c[pp]);
        }
        __nv_bfloat16* rc_dst = g_hb + ((size_t)(dir * TT + t) * BB + rc_bl) * HH + hc0 + 2 * rc_q;
        *(__nv_bfloat162*)rc_dst = __nv_bfloat162(__float2bfloat16_rn(rc_h[0]), __float2bfloat16_rn(rc_h[1]));
        *(__nv_bfloat162*)(rc_dst + 8 * HH) = __nv_bfloat162(__float2bfloat16_rn(rc_h[2]), __float2bfloat16_rn(rc_h[3]));

        grid_sync_fast();
    }
}

// =============== kernel 3: emissions, warp per (t, b) ================================
__global__ void __launch_bounds__(128) emissions_k(
    const float* __restrict__ linW, const float* __restrict__ linb)
{
    const int em_t = blockIdx.y;
    const int em_b = blockIdx.x * 4 + (threadIdx.x >> 5);
    const int em_lane = threadIdx.x & 31;

    float em_acc[NK];
#pragma unroll
    for (int kc = 0; kc < NK; kc++) em_acc[kc] = 0.0f;

#pragma unroll
    for (int dd = 0; dd < 2; dd++) {
        const __nv_bfloat162* em_hp = (const __nv_bfloat162*)(g_hb + ((size_t)(dd * TT + em_t) * BB + em_b) * HH);
        const int em_wo = dd * HH;
#pragma unroll
        for (int it = 0; it < 8; it++) {
            int em_k = it * 64 + em_lane * 2;
            __nv_bfloat162 em_hv = em_hp[it * 32 + em_lane];
            float em_hx = __bfloat162float(em_hv.x);
            float em_hy = __bfloat162float(em_hv.y);
#pragma unroll
            for (int kc = 0; kc < NK; kc++) {
                const float* em_wr = linW + kc * (2 * HH) + em_wo + em_k;
                em_acc[kc] += em_hx * __ldg(em_wr) + em_hy * __ldg(em_wr + 1);
            }
        }
    }
#pragma unroll
    for (int kc = 0; kc < NK; kc++) {
#pragma unroll
        for (int o = 16; o; o >>= 1) em_acc[kc] += __shfl_xor_sync(0xffffffffu, em_acc[kc], o);
    }
    if (em_lane == 0) {
#pragma unroll
        for (int kc = 0; kc < NK; kc++) g_em[((size_t)em_t * BB + em_b) * NK + kc] = em_acc[kc] + linb[kc];
    }
}

// =============== kernel 4: CRF score + forward algorithm =============================
__global__ void __launch_bounds__(32) crf_k(
    const int* __restrict__ labels, const float* __restrict__ trans,
    const float* __restrict__ startT, const float* __restrict__ endT)
{
    const int cb = blockIdx.x;
    const int cl = threadIdx.x;

    float csc = 0.0f;
    for (int ct = cl; ct < TT; ct += 32) {
        int clt = labels[cb * TT + ct];
        csc += g_em[((size_t)ct * BB + cb) * NK + clt];
        if (ct < TT - 1) csc += trans[clt * NK + labels[cb * TT + ct + 1]];
    }
#pragma unroll
    for (int o = 16; o; o >>= 1) csc += __shfl_down_sync(0xffffffffu, csc, o);

    const int ck = (cl < NK) ? cl : 0;
    float ctr[NK];
#pragma unroll
    for (int cj = 0; cj < NK; cj++) ctr[cj] = trans[cj * NK + ck];

    float calpha = startT[ck] + g_em[(size_t)cb * NK + ck];
    for (int ct = 1; ct < TT; ct++) {
        float cv[NK];
        float cm = -3.0e38f;
#pragma unroll
        for (int cj = 0; cj < NK; cj++) {
            cv[cj] = __shfl_sync(0xffffffffu, calpha, cj) + ctr[cj];
            cm = fmaxf(cm, cv[cj]);
        }
        float cs = 0.0f;
#pragma unroll
        for (int cj = 0; cj < NK; cj++) cs += expf(cv[cj] - cm);
        calpha = cm + logf(cs) + g_em[((size_t)ct * BB + cb) * NK + ck];
    }
    float cav = calpha + endT[ck];
    float cmm = cav;
#pragma unroll
    for (int cj = 0; cj < NK; cj++) cmm = fmaxf(cmm, __shfl_sync(0xffffffffu, cav, cj));
    float ce = (cl < NK) ? expf(cav - cmm) : 0.0f;
#pragma unroll
    for (int o = 16; o; o >>= 1) ce += __shfl_down_sync(0xffffffffu, ce, o);

    if (cl == 0) {
        float clogZ = cmm + logf(ce);
        float cscore = csc + startT[labels[cb * TT]] + endT[labels[cb * TT + TT - 1]];
        g_lossB[cb] = cscore - clogZ;
    }
}

// =============== kernel 5: deterministic final reduce ================================
__global__ void __launch_bounds__(128) final_reduce(float* out)
{
    __shared__ float fr_s[128];
    fr_s[threadIdx.x] = g_lossB[threadIdx.x];
    __syncthreads();
    for (int o = 64; o; o >>= 1) {
        if (threadIdx.x < o) fr_s[threadIdx.x] += fr_s[threadIdx.x + o];
        __syncthreads();
    }
    if (threadIdx.x == 0) out[0] = -fr_s[0];
}

// =============== launch ==============================================================
extern "C" void kernel_launch(void* const* d_in, const int* in_sizes, int n_in,
                              void* d_out, int out_size)
{
    const int*   inputData = (const int*)d_in[0];
    const int*   labels    = (const int*)d_in[1];
    const float* embed     = (const float*)d_in[2];
    const float* WihF = (const float*)d_in[3];
    const float* WhhF = (const float*)d_in[4];
    const float* bihF = (const float*)d_in[5];
    const float* bhhF = (const float*)d_in[6];
    const float* WihB = (const float*)d_in[7];
    const float* WhhB = (const float*)d_in[8];
    const float* bihB = (const float*)d_in[9];
    const float* bhhB = (const float*)d_in[10];
    const float* linW = (const float*)d_in[11];
    const float* linb = (const float*)d_in[12];
    const float* trans = (const float*)d_in[13];
    const float* startT = (const float*)d_in[14];
    const float* endT   = (const float*)d_in[15];

    cudaFuncSetAttribute(input_gemm, cudaFuncAttributeMaxDynamicSharedMemorySize, 2 * 128 * SP2 * 2);
    cudaFuncSetAttribute(recurrent, cudaFuncAttributeMaxDynamicSharedMemorySize, 128 * SPH * 2 + 32 * SPW * 2);

    input_gemm<<<dim3(16, 128, 2), 256, 2 * 128 * SP2 * 2>>>(inputData, embed, WihF, WihB, bihF, bhhF, bihB, bhhB);

    recurrent<<<NCTAS, 256, 128 * SPH * 2 + 32 * SPW * 2>>>(WhhF, WhhB);

    emissions_k<<<dim3(32, TT), 128>>>(linW, linb);
    crf_k<<<BB, 32>>>(labels, trans, startT, endT);
    final_reduce<<<1, 128>>>((float*)d_out);
}

// round 10
// speedup vs baseline: 3.1326x; 1.1375x over previous
#include <cuda_runtime.h>
#include <cuda_bf16.h>
#include <math.h>

#define TT 256
#define BB 128
#define EE 256
#define HH 512
#define G4 2048
#define NK 7
#define NCTAS 128

#define SPH 520
#define SPW 520
#define SP2 264

__device__ float g_G[134217728];
__device__ __nv_bfloat16 g_hb[33554432];
__device__ float g_em[229376];
__device__ float g_lossB[BB];
__device__ unsigned g_flag[8];   // [dir*4 + chunk], monotonic publish counters

__device__ __forceinline__ float tanh_fast(float x) {
    float y;
    asm("tanh.approx.f32 %0, %1;" : "=f"(y) : "f"(x));
    return y;
}
__device__ __forceinline__ float sigmoid_fast(float x) {
    return 0.5f * tanh_fast(0.5f * x) + 0.5f;
}

__device__ __forceinline__ unsigned smem_u32(const void* p) {
    return (unsigned)__cvta_generic_to_shared(p);
}

__device__ __forceinline__ void ldsm4(unsigned addr, unsigned* r) {
    asm volatile("ldmatrix.sync.aligned.m8n8.x4.shared.b16 {%0,%1,%2,%3}, [%4];"
                 : "=r"(r[0]), "=r"(r[1]), "=r"(r[2]), "=r"(r[3]) : "r"(addr));
}

__device__ __forceinline__ void mma_bf16(float* c, const unsigned* a, unsigned b0, unsigned b1) {
    asm volatile(
        "mma.sync.aligned.m16n8k16.row.col.f32.bf16.bf16.f32 "
        "{%0,%1,%2,%3},{%4,%5,%6,%7},{%8,%9},{%0,%1,%2,%3};"
        : "+f"(c[0]), "+f"(c[1]), "+f"(c[2]), "+f"(c[3])
        : "r"(a[0]), "r"(a[1]), "r"(a[2]), "r"(a[3]), "r"(b0), "r"(b1));
}

__device__ __forceinline__ void cp_async16(unsigned saddr, const void* gaddr) {
    asm volatile("cp.async.cg.shared.global [%0], [%1], 16;" :: "r"(saddr), "l"(gaddr));
}
__device__ __forceinline__ void cp_commit() { asm volatile("cp.async.commit_group;"); }
__device__ __forceinline__ void cp_wait1() { asm volatile("cp.async.wait_group 1;"); }
__device__ __forceinline__ void cp_wait0() { asm volatile("cp.async.wait_group 0;"); }

__device__ __forceinline__ void cvt4_bf16(__nv_bfloat16* d, float4 v) {
    d[0] = __float2bfloat16_rn(v.x);
    d[1] = __float2bfloat16_rn(v.y);
    d[2] = __float2bfloat16_rn(v.z);
    d[3] = __float2bfloat16_rn(v.w);
}

__device__ __forceinline__ unsigned ldsmA_off(int warp, int lane, int stride) {
    int ar = warp * 16 + (lane & 15);
    int ak = (lane >> 4) * 8;
    return (unsigned)((ar * stride + ak) * 2);
}
__device__ __forceinline__ unsigned ldsmB_off(int lane, int stride) {
    int br = ((lane >> 4) << 3) + (lane & 7);
    int bk = ((lane >> 3) & 1) * 8;
    return (unsigned)((br * stride + bk) * 2);
}

__device__ __forceinline__ void wait_flag_ge(const unsigned* fp, unsigned need) {
    if ((threadIdx.x & 31) == 0) {
        unsigned fv = 0;
        do {
            asm volatile("ld.acquire.gpu.u32 %0, [%1];" : "=r"(fv) : "l"(fp) : "memory");
        } while (fv < need);
    }
    __syncwarp();
}

__device__ __forceinline__ void rc_mma_chunk(int ks0, unsigned haddr, unsigned w0,
                                             unsigned w1, float (*acc)[4]) {
#pragma unroll
    for (int kk = 0; kk < 8; kk++) {
        int ks = ks0 + kk;
        unsigned maf[4];
        unsigned mbf[4];
        unsigned mcf[4];
        ldsm4(haddr + ks * 32, maf);
        ldsm4(w0 + ks * 32, mbf);
        ldsm4(w1 + ks * 32, mcf);
        mma_bf16(acc[0], maf, mbf[0], mbf[1]);
        mma_bf16(acc[1], maf, mbf[2], mbf[3]);
        mma_bf16(acc[2], maf, mcf[0], mcf[1]);
        mma_bf16(acc[3], maf, mcf[2], mcf[3]);
    }
}

// =============== kernel 0: reset publish flags (per launch, graph-safe) ==============
__global__ void reset_flags_k() {
    if (threadIdx.x < 8) g_flag[threadIdx.x] = 0u;
}

// =============== kernel 1: embedding gather + input GEMM (bf16 mma) + bias ===========
__global__ void __launch_bounds__(256, 1) input_gemm(
    const int* __restrict__ inputData, const float* __restrict__ embed,
    const float* __restrict__ WihF, const float* __restrict__ WihB,
    const float* __restrict__ bihF, const float* __restrict__ bhhF,
    const float* __restrict__ bihB, const float* __restrict__ bhhB)
{
    extern __shared__ __align__(16) char ig_smem[];
    __nv_bfloat16* ig_As = (__nv_bfloat16*)ig_smem;
    __nv_bfloat16* ig_Xs = (__nv_bfloat16*)(ig_smem + 128 * SP2 * 2);
    __shared__ int ig_rows[128];

    const int dir = blockIdx.z;
    const int t0  = blockIdx.y * 2;
    const int j0  = blockIdx.x * 128;
    const float* __restrict__ Wih = dir ? WihB : WihF;
    const float* __restrict__ bih = dir ? bihB : bihF;
    const float* __restrict__ bhh = dir ? bhhB : bhhF;

    const int ig_tid  = threadIdx.x;
    const int ig_warp = ig_tid >> 5;
    const int ig_lane = ig_tid & 31;

    for (int wi = ig_tid; wi < 128 * 64; wi += 256) {
        int wr = wi >> 6;
        int wk = (wi & 63) * 4;
        float4 wv = *(const float4*)(Wih + (size_t)(j0 + wr) * EE + wk);
        cvt4_bf16(ig_As + wr * SP2 + wk, wv);
    }

    const unsigned ig_aaddr = smem_u32(ig_As) + ldsmA_off(ig_warp, ig_lane, SP2);
    const unsigned ig_xaddr = smem_u32(ig_Xs) + ldsmB_off(ig_lane, SP2);

    const int ig_q = ig_lane & 3;
    const int ig_rq = ig_lane >> 2;
    const int ig_j = j0 + ig_warp * 16 + ig_rq;
    const float ig_bias0 = bih[ig_j] + bhh[ig_j];
    const float ig_bias1 = bih[ig_j + 8] + bhh[ig_j + 8];

    for (int tt = 0; tt < 2; tt++) {
        const int t = t0 + tt;
        if (ig_tid < 128) ig_rows[ig_tid] = inputData[t * BB + ig_tid];
        __syncthreads();

        for (int xi = ig_tid; xi < 128 * 64; xi += 256) {
            int xb = xi >> 6;
            int xk = (xi & 63) * 4;
            float4 xv = *(const float4*)(embed + (size_t)ig_rows[xb] * EE + xk);
            cvt4_bf16(ig_Xs + xb * SP2 + xk, xv);
        }
        __syncthreads();

        float ig_acc[16][4];
#pragma unroll
        for (int ci = 0; ci < 16; ci++) {
#pragma unroll
            for (int cj = 0; cj < 4; cj++) ig_acc[ci][cj] = 0.0f;
        }

#pragma unroll
        for (int ks = 0; ks < 16; ks++) {
            unsigned ig_af[4];
            ldsm4(ig_aaddr + ks * 32, ig_af);
#pragma unroll
            for (int bt = 0; bt < 8; bt++) {
                unsigned ig_xf[4];
                ldsm4(ig_xaddr + bt * (16 * SP2 * 2) + ks * 32, ig_xf);
                mma_bf16(ig_acc[2 * bt], ig_af, ig_xf[0], ig_xf[1]);
                mma_bf16(ig_acc[2 * bt + 1], ig_af, ig_xf[2], ig_xf[3]);
            }
        }

        const size_t ig_base0 = ((size_t)(dir * TT + t) * G4 + ig_j) * BB;
        const size_t ig_base1 = ig_base0 + 8 * BB;
#pragma unroll
        for (int nt = 0; nt < 16; nt++) {
            int ob = nt * 8 + 2 * ig_q;
            *(float2*)(g_G + ig_base0 + ob) = make_float2(ig_acc[nt][0] + ig_bias0, ig_acc[nt][1] + ig_bias0);
            *(float2*)(g_G + ig_base1 + ob) = make_float2(ig_acc[nt][2] + ig_bias1, ig_acc[nt][3] + ig_bias1);
        }
        __syncthreads();
    }
}

// =============== kernel 2: persistent BiLSTM recurrence (dataflow sync) ==============
__global__ void __launch_bounds__(256, 1) recurrent(
    const float* __restrict__ WhhF, const float* __restrict__ WhhB)
{
    extern __shared__ __align__(16) char rc_smem[];
    __nv_bfloat16* rc_hs = (__nv_bfloat16*)rc_smem;
    __nv_bfloat16* rc_ws = (__nv_bfloat16*)(rc_smem + 128 * SPH * 2);

    const int rc_tid  = threadIdx.x;
    const int rc_warp = rc_tid >> 5;
    const int rc_lane = rc_tid & 31;
    const int rc_bid  = blockIdx.x;
    const int dir     = rc_bid >> 6;
    const int hc0     = (rc_bid & 63) * 8;
    const int rc_myck = (rc_bid & 63) >> 4;
    const float* __restrict__ Whh = dir ? WhhB : WhhF;

    for (int wi = rc_tid; wi < 32 * 512; wi += 256) {
        int wrow = wi >> 9;
        int wk = wi & 511;
        int wj = (wrow >> 3) * HH + hc0 + (wrow & 7);
        rc_ws[wrow * SPW + wk] = __float2bfloat16_rn(Whh[(size_t)wj * HH + wk]);
    }
    __syncthreads();

    const unsigned rc_hbase = smem_u32(rc_hs);
    const unsigned rc_haddr = rc_hbase + ldsmA_off(rc_warp, rc_lane, SPH);
    const unsigned rc_w0 = smem_u32(rc_ws) + ldsmB_off(rc_lane, SPW);
    const unsigned rc_w1 = rc_w0 + 16 * SPW * 2;

    const int rc_q  = rc_lane & 3;
    const int rc_rq = rc_lane >> 2;
    const int rc_bl = rc_warp * 16 + rc_rq;

    float rc_c[4] = {0.f, 0.f, 0.f, 0.f};

    for (int s = 0; s < TT; s++) {
        const int t = dir ? (TT - 1 - s) : s;

        const float* rc_Gp = g_G + (size_t)(dir * TT + t) * G4 * BB;
        float rc_pg[4][4];
#pragma unroll
        for (int gi = 0; gi < 4; gi++) {
#pragma unroll
            for (int pp = 0; pp < 4; pp++) {
                int qb = rc_bl + (pp >> 1) * 8;
                int qh = 2 * rc_q + (pp & 1);
                rc_pg[gi][pp] = __ldcg(rc_Gp + (size_t)(gi * HH + hc0 + qh) * BB + qb);
            }
        }

        float rc_acc[4][4];
#pragma unroll
        for (int gi = 0; gi < 4; gi++) {
#pragma unroll
            for (int pi = 0; pi < 4; pi++) rc_acc[gi][pi] = 0.0f;
        }

        if (s > 0) {
            const int tp = dir ? (t + 1) : (t - 1);
            const uint4* rc_src = (const uint4*)(g_hb + (size_t)(dir * TT + tp) * BB * HH);
            const unsigned rc_need = (unsigned)(16 * s);
#pragma unroll
            for (int ck = 0; ck < 4; ck++) {
                wait_flag_ge(&g_flag[dir * 4 + ck], rc_need);
#pragma unroll
                for (int li = 0; li < 8; li++) {
                    int lv = li * 256 + rc_tid;
                    int lrow = lv >> 4;
                    int lu = lv & 15;
                    unsigned lsa = rc_hbase + (unsigned)((lrow * SPH + ck * 128 + lu * 8) * 2);
                    cp_async16(lsa, (const void*)(rc_src + lrow * 64 + ck * 16 + lu));
                }
                cp_commit();
                if (ck > 0) {
                    cp_wait1();
                    __syncthreads();
                    rc_mma_chunk((ck - 1) * 8, rc_haddr, rc_w0, rc_w1, rc_acc);
                }
            }
            cp_wait0();
            __syncthreads();
            rc_mma_chunk(24, rc_haddr, rc_w0, rc_w1, rc_acc);
        }

        float rc_h[4];
#pragma unroll
        for (int pp = 0; pp < 4; pp++) {
            float pgi = rc_pg[0][pp] + rc_acc[0][pp];
            float pgf = rc_pg[1][pp] + rc_acc[1][pp];
            float pgg = rc_pg[2][pp] + rc_acc[2][pp];
            float pgo = rc_pg[3][pp] + rc_acc[3][pp];
            float piv = sigmoid_fast(pgi);
            float pfv = sigmoid_fast(pgf);
            float pgv = tanh_fast(pgg);
            float pov = sigmoid_fast(pgo);
            rc_c[pp] = pfv * rc_c[pp] + piv * pgv;
            rc_h[pp] = pov * tanh_fast(rc_c[pp]);
        }
        __nv_bfloat16* rc_dst = g_hb + ((size_t)(dir * TT + t) * BB + rc_bl) * HH + hc0 + 2 * rc_q;
        *(__nv_bfloat162*)rc_dst = __nv_bfloat162(__float2bfloat16_rn(rc_h[0]), __float2bfloat16_rn(rc_h[1]));
        *(__nv_bfloat162*)(rc_dst + 8 * HH) = __nv_bfloat162(__float2bfloat16_rn(rc_h[2]), __float2bfloat16_rn(rc_h[3]));

        __syncthreads();
        if (rc_tid == 0) {
            unsigned rc_pd;
            asm volatile("atom.add.release.gpu.u32 %0, [%1], 1;"
                         : "=r"(rc_pd) : "l"(&g_flag[dir * 4 + rc_myck]) : "memory");
        }
    }
}

// =============== kernel 3: emissions, warp per (t, b) ================================
__global__ void __launch_bounds__(128) emissions_k(
    const float* __restrict__ linW, const float* __restrict__ linb)
{
    const int em_t = blockIdx.y;
    const int em_b = blockIdx.x * 4 + (threadIdx.x >> 5);
    const int em_lane = threadIdx.x & 31;

    float em_acc[NK];
#pragma unroll
    for (int kc = 0; kc < NK; kc++) em_acc[kc] = 0.0f;

#pragma unroll
    for (int dd = 0; dd < 2; dd++) {
        const __nv_bfloat162* em_hp = (const __nv_bfloat162*)(g_hb + ((size_t)(dd * TT + em_t) * BB + em_b) * HH);
        const int em_wo = dd * HH;
#pragma unroll
        for (int it = 0; it < 8; it++) {
            int em_k = it * 64 + em_lane * 2;
            __nv_bfloat162 em_hv = em_hp[it * 32 + em_lane];
            float em_hx = __bfloat162float(em_hv.x);
            float em_hy = __bfloat162float(em_hv.y);
#pragma unroll
            for (int kc = 0; kc < NK; kc++) {
                const float* em_wr = linW + kc * (2 * HH) + em_wo + em_k;
                em_acc[kc] += em_hx * __ldg(em_wr) + em_hy * __ldg(em_wr + 1);
            }
        }
    }
#pragma unroll
    for (int kc = 0; kc < NK; kc++) {
#pragma unroll
        for (int o = 16; o; o >>= 1) em_acc[kc] += __shfl_xor_sync(0xffffffffu, em_acc[kc], o);
    }
    if (em_lane == 0) {
#pragma unroll
        for (int kc = 0; kc < NK; kc++) g_em[((size_t)em_t * BB + em_b) * NK + kc] = em_acc[kc] + linb[kc];
    }
}

// =============== kernel 4: CRF score + forward algorithm =============================
__global__ void __launch_bounds__(32) crf_k(
    const int* __restrict__ labels, const float* __restrict__ trans,
    const float* __restrict__ startT, const float* __restrict__ endT)
{
    const int cb = blockIdx.x;
    const int cl = threadIdx.x;

    float csc = 0.0f;
    for (int ct = cl; ct < TT; ct += 32) {
        int clt = labels[cb * TT + ct];
        csc += g_em[((size_t)ct * BB + cb) * NK + clt];
        if (ct < TT - 1) csc += trans[clt * NK + labels[cb * TT + ct + 1]];
    }
#pragma unroll
    for (int o = 16; o; o >>= 1) csc += __shfl_down_sync(0xffffffffu, csc, o);

    const int ck = (cl < NK) ? cl : 0;
    float ctr[NK];
#pragma unroll
    for (int cj = 0; cj < NK; cj++) ctr[cj] = trans[cj * NK + ck];

    float calpha = startT[ck] + g_em[(size_t)cb * NK + ck];
    for (int ct = 1; ct < TT; ct++) {
        float cv[NK];
        float cm = -3.0e38f;
#pragma unroll
        for (int cj = 0; cj < NK; cj++) {
            cv[cj] = __shfl_sync(0xffffffffu, calpha, cj) + ctr[cj];
            cm = fmaxf(cm, cv[cj]);
        }
        float cs = 0.0f;
#pragma unroll
        for (int cj = 0; cj < NK; cj++) cs += expf(cv[cj] - cm);
        calpha = cm + logf(cs) + g_em[((size_t)ct * BB + cb) * NK + ck];
    }
    float cav = calpha + endT[ck];
    float cmm = cav;
#pragma unroll
    for (int cj = 0; cj < NK; cj++) cmm = fmaxf(cmm, __shfl_sync(0xffffffffu, cav, cj));
    float ce = (cl < NK) ? expf(cav - cmm) : 0.0f;
#pragma unroll
    for (int o = 16; o; o >>= 1) ce += __shfl_down_sync(0xffffffffu, ce, o);

    if (cl == 0) {
        float clogZ = cmm + logf(ce);
        float cscore = csc + startT[labels[cb * TT]] + endT[labels[cb * TT + TT - 1]];
        g_lossB[cb] = cscore - clogZ;
    }
}

// =============== kernel 5: deterministic final reduce ================================
__global__ void __launch_bounds__(128) final_reduce(float* out)
{
    __shared__ float fr_s[128];
    fr_s[threadIdx.x] = g_lossB[threadIdx.x];
    __syncthreads();
    for (int o = 64; o; o >>= 1) {
        if (threadIdx.x < o) fr_s[threadIdx.x] += fr_s[threadIdx.x + o];
        __syncthreads();
    }
    if (threadIdx.x == 0) out[0] = -fr_s[0];
}

// =============== launch ==============================================================
extern "C" void kernel_launch(void* const* d_in, const int* in_sizes, int n_in,
                              void* d_out, int out_size)
{
    const int*   inputData = (const int*)d_in[0];
    const int*   labels    = (const int*)d_in[1];
    const float* embed     = (const float*)d_in[2];
    const float* WihF = (const float*)d_in[3];
    const float* WhhF = (const float*)d_in[4];
    const float* bihF = (const float*)d_in[5];
    const float* bhhF = (const float*)d_in[6];
    const float* WihB = (const float*)d_in[7];
    const float* WhhB = (const float*)d_in[8];
    const float* bihB = (const float*)d_in[9];
    const float* bhhB = (const float*)d_in[10];
    const float* linW = (const float*)d_in[11];
    const float* linb = (const float*)d_in[12];
    const float* trans = (const float*)d_in[13];
    const float* startT = (const float*)d_in[14];
    const float* endT   = (const float*)d_in[15];

    cudaFuncSetAttribute(input_gemm, cudaFuncAttributeMaxDynamicSharedMemorySize, 2 * 128 * SP2 * 2);
    cudaFuncSetAttribute(recurrent, cudaFuncAttributeMaxDynamicSharedMemorySize, 128 * SPH * 2 + 32 * SPW * 2);

    reset_flags_k<<<1, 32>>>();

    input_gemm<<<dim3(16, 128, 2), 256, 2 * 128 * SP2 * 2>>>(inputData, embed, WihF, WihB, bihF, bhhF, bihB, bhhB);

    recurrent<<<NCTAS, 256, 128 * SPH * 2 + 32 * SPW * 2>>>(WhhF, WhhB);

    emissions_k<<<dim3(32, TT), 128>>>(linW, linb);
    crf_k<<<BB, 32>>>(labels, trans, startT, endT);
    final_reduce<<<1, 128>>>((float*)d_out);
}